// round 12
// baseline (speedup 1.0000x reference)
#include <cuda_runtime.h>
#include <cstdint>
#include <math.h>

// Problem constants
#define HH    200
#define WW    200
#define HWSZ  40000
#define CIN   256
#define BB    2
#define CG    64      // channels per group (both real DCN groups and conv pseudo-groups)
#define NGK   36      // 4 groups * 9 taps
#define OMCH  108     // offset-mask conv output channels

// Scratch (static device arrays -- no runtime allocation)
__device__ float g_om[BB * OMCH * HWSZ];          // 34.56 MB: conv output (raw, pre-sigmoid)
__device__ float g_wt_dcn[NGK * CG * 256];        // 2.36 MB: w_dcn transposed [gk][cg][oc]
__device__ float g_wt_om[NGK * CG * 128];         // 1.18 MB: w_om transposed, oc padded to 128

typedef unsigned long long ull;

__device__ __forceinline__ ull fdup(float x) {
    ull r; asm("mov.b64 %0, {%1, %1};" : "=l"(r) : "f"(x)); return r;
}
__device__ __forceinline__ void fma2(ull& d, ull a, ull b) {
    // d = a*b + d, packed 2x fp32 (Blackwell f32x2 pipe: 2 FMA per FFMA2 issue)
    asm("fma.rn.f32x2 %0, %1, %2, %0;" : "+l"(d) : "l"(a), "l"(b));
}
__device__ __forceinline__ float2 unpk(ull a) {
    float2 r; asm("mov.b64 {%0, %1}, %2;" : "=f"(r.x), "=f"(r.y) : "l"(a)); return r;
}

// ---------------------------------------------------------------------------
// Weight transposes: [O][C][9] -> [gk][cg][oc] (oc contiguous => coalesced
// smem tile fills in the GEMM kernel).
// ---------------------------------------------------------------------------
__global__ void k_transpose_dcn(const float* __restrict__ w, float* __restrict__ wt) {
    int tid = blockIdx.x * 256 + threadIdx.x;
    if (tid >= NGK * CG * 256) return;
    int o  = tid & 255;
    int cg = (tid >> 8) & 63;
    int gk = tid >> 14;
    int g = gk / 9, k = gk - g * 9;
    wt[tid] = w[(o * CIN + g * CG + cg) * 9 + k];
}

__global__ void k_transpose_om(const float* __restrict__ w, float* __restrict__ wt) {
    int tid = blockIdx.x * 256 + threadIdx.x;
    if (tid >= NGK * CG * 128) return;
    int o  = tid & 127;
    int cg = (tid >> 7) & 63;
    int gk = tid >> 13;
    int g = gk / 9, k = gk - g * 9;
    wt[tid] = (o < OMCH) ? w[(o * CIN + g * CG + cg) * 9 + k] : 0.0f;
}

// ---------------------------------------------------------------------------
// Unified gather + GEMM kernel.
//   Tile: OCT output channels x 64 consecutive pixels (linear over B*H*W;
//         80000 % 64 == 0 and the batch boundary (40000) is tile-aligned).
//   256 threads: to = t / PIX_THR handles 8 oc (4 f32x2 pairs),
//                tp = t % PIX_THR handles PIX_PER = 64/PIX_THR pixels.
//   Per (g,k) iteration:
//     - per-pixel sampling meta in registers (pix = t & 63, 4x redundant)
//     - W tile [64 cg][OCT] -> smem (coalesced from transposed weights)
//     - gather v[64 cg][64 px] -> smem as duplicated float2 (broadcast operand
//       pre-packed => inner loop has zero mov.b64)
//     - register-tile GEMM with fma.rn.f32x2 (acc pairs along oc)
//   DEFORM=true : bilinear sample with offsets/sigmoid(mask) from g_om, ReLU.
//   DEFORM=false: identity 3x3 taps (the offset-mask conv itself), +bias.
// ---------------------------------------------------------------------------
template <int OCT, int PIX_THR, bool DEFORM, int MAXB>
__global__ void __launch_bounds__(256, MAXB)
k_fused(const float* __restrict__ x, const float* __restrict__ wt,
        const float* __restrict__ om, const float* __restrict__ bias,
        float* __restrict__ out, int o_valid)
{
    constexpr int PIX_PER = 64 / PIX_THR;
    extern __shared__ float smem[];
    float*  sWt  = smem;                           // 64 * OCT floats
    float2* vdup = (float2*)(smem + 64 * OCT);     // 64 * 64 float2 (duplicated)

    const int t   = threadIdx.x;
    const int tp  = t % PIX_THR;
    const int to  = t / PIX_THR;
    const int pix = t & 63;

    const int p0 = blockIdx.x * 64;
    const int b  = (p0 >= HWSZ) ? 1 : 0;
    const int hw = p0 - b * HWSZ + pix;
    const int h  = hw / WW;
    const int w  = hw - h * WW;

    ull acc[4][PIX_PER];
#pragma unroll
    for (int i = 0; i < 4; i++)
#pragma unroll
        for (int j = 0; j < PIX_PER; j++) acc[i][j] = 0ull;

    const int xgbase = b * CIN * HWSZ;
    const int ombase = b * OMCH * HWSZ + hw;

    for (int gk = 0; gk < NGK; gk++) {
        const int g  = gk / 9;
        const int k  = gk - g * 9;
        const int ki = k / 3;
        const int kj = k - ki * 3;

        // ---- per-pixel sampling metadata (registers) ----
        int   a00 = 0, a01 = 0, a10 = 0, a11 = 0;
        float w00, w01 = 0.f, w10 = 0.f, w11 = 0.f;
        if (DEFORM) {
            float dy = om[ombase + (g * 18 + 2 * k)     * HWSZ];
            float dx = om[ombase + (g * 18 + 2 * k + 1) * HWSZ];
            float mr = om[ombase + (72 + g * 9 + k)     * HWSZ];
            float m  = 1.0f / (1.0f + expf(-mr));
            float py = (float)(h - 1 + ki) + dy;
            float px = (float)(w - 1 + kj) + dx;
            float fy = floorf(py), fx = floorf(px);
            int   y0 = (int)fy,    x0 = (int)fx;
            float wy = py - fy,    wx = px - fx;
            bool vy0 = (unsigned)y0       < HH, vy1 = (unsigned)(y0 + 1) < HH;
            bool vx0 = (unsigned)x0       < WW, vx1 = (unsigned)(x0 + 1) < WW;
            float oy = 1.0f - wy, ox = 1.0f - wx;
            w00 = (vy0 && vx0) ? m * oy * ox : 0.0f;
            w01 = (vy0 && vx1) ? m * oy * wx : 0.0f;
            w10 = (vy1 && vx0) ? m * wy * ox : 0.0f;
            w11 = (vy1 && vx1) ? m * wy * wx : 0.0f;
            int cy0 = min(max(y0, 0), HH - 1), cy1 = min(max(y0 + 1, 0), HH - 1);
            int cx0 = min(max(x0, 0), WW - 1), cx1 = min(max(x0 + 1, 0), WW - 1);
            a00 = cy0 * WW + cx0; a01 = cy0 * WW + cx1;
            a10 = cy1 * WW + cx0; a11 = cy1 * WW + cx1;
        } else {
            int y0 = h - 1 + ki, x0 = w - 1 + kj;
            bool inb = ((unsigned)y0 < HH) && ((unsigned)x0 < WW);
            w00 = inb ? 1.0f : 0.0f;
            a00 = min(max(y0, 0), HH - 1) * WW + min(max(x0, 0), WW - 1);
        }

        // ---- W tile -> smem (coalesced float4) ----
        {
            const float4* src = (const float4*)(wt + gk * 64 * OCT);
            float4*       dst = (float4*)sWt;
#pragma unroll
            for (int j = 0; j < (64 * OCT) / (4 * 256); j++)
                dst[t + j * 256] = src[t + j * 256];
        }

        // ---- gather v[cg][pix] (thread owns fixed pix, strides cg by 4) ----
        {
            const float* pl = x + xgbase + (g * CG + (t >> 6)) * HWSZ;
#pragma unroll
            for (int e = 0; e < 16; e++) {
                float val;
                if (DEFORM) {
                    val = w00 * pl[a00] + w01 * pl[a01]
                        + w10 * pl[a10] + w11 * pl[a11];
                } else {
                    val = w00 * pl[a00];
                }
                vdup[((t >> 6) + 4 * e) * 64 + pix] = make_float2(val, val);
                pl += 4 * HWSZ;
            }
        }
        __syncthreads();

        // ---- register-tile GEMM: out[8 oc][PIX_PER px] += W[.][cg] * v[cg][.] ----
#pragma unroll 4
        for (int cg = 0; cg < 64; cg++) {
            const ulonglong2* wr = (const ulonglong2*)(sWt + cg * OCT + to * 8);
            ulonglong2 wa = wr[0];
            ulonglong2 wb = wr[1];
            const ulonglong2* vr = (const ulonglong2*)(vdup + cg * 64 + tp * PIX_PER);
#pragma unroll
            for (int q = 0; q < PIX_PER / 2; q++) {
                ulonglong2 vv = vr[q];
                fma2(acc[0][2 * q],     wa.x, vv.x);
                fma2(acc[0][2 * q + 1], wa.x, vv.y);
                fma2(acc[1][2 * q],     wa.y, vv.x);
                fma2(acc[1][2 * q + 1], wa.y, vv.y);
                fma2(acc[2][2 * q],     wb.x, vv.x);
                fma2(acc[2][2 * q + 1], wb.x, vv.y);
                fma2(acc[3][2 * q],     wb.y, vv.x);
                fma2(acc[3][2 * q + 1], wb.y, vv.y);
            }
        }
        __syncthreads();
    }

    // ---- epilogue: unpack f32x2, bias/ReLU, vectorized coalesced stores ----
    const int hwS = (p0 - b * HWSZ) + tp * PIX_PER;
#pragma unroll
    for (int pi = 0; pi < 4; pi++) {
        float v0[PIX_PER], v1[PIX_PER];
#pragma unroll
        for (int j = 0; j < PIX_PER; j++) {
            float2 u = unpk(acc[pi][j]);
            v0[j] = u.x; v1[j] = u.y;
        }
#pragma unroll
        for (int half = 0; half < 2; half++) {
            int o = to * 8 + pi * 2 + half;
            if (o < o_valid) {
                float bv = 0.0f;
                if (!DEFORM) bv = bias[o];
                float* op = out + (size_t)(b * o_valid + o) * HWSZ + hwS;
                const float* vv = half ? v1 : v0;
#pragma unroll
                for (int q = 0; q < PIX_PER / 4; q++) {
                    float4 r;
                    r.x = vv[4 * q + 0] + bv;
                    r.y = vv[4 * q + 1] + bv;
                    r.z = vv[4 * q + 2] + bv;
                    r.w = vv[4 * q + 3] + bv;
                    if (DEFORM) {
                        r.x = fmaxf(r.x, 0.0f); r.y = fmaxf(r.y, 0.0f);
                        r.z = fmaxf(r.z, 0.0f); r.w = fmaxf(r.w, 0.0f);
                    }
                    ((float4*)op)[q] = r;
                }
            }
        }
    }
}

// ---------------------------------------------------------------------------
extern "C" void kernel_launch(void* const* d_in, const int* in_sizes, int n_in,
                              void* d_out, int out_size)
{
    const float* x     = (const float*)d_in[0];   // [2,256,200,200]
    const float* w_om  = (const float*)d_in[1];   // [108,256,3,3]
    const float* b_om  = (const float*)d_in[2];   // [108]
    const float* w_dcn = (const float*)d_in[3];   // [256,256,3,3]
    float* out = (float*)d_out;                   // [2,256,200,200]

    float *om, *wtd, *wto;
    cudaGetSymbolAddress((void**)&om,  g_om);
    cudaGetSymbolAddress((void**)&wtd, g_wt_dcn);
    cudaGetSymbolAddress((void**)&wto, g_wt_om);

    const int smem_conv = 64 * 128 * 4 + 64 * 64 * 8;   // 65536
    const int smem_dcn  = 64 * 256 * 4 + 64 * 64 * 8;   // 98304
    cudaFuncSetAttribute(k_fused<128, 16, false, 3>,
                         cudaFuncAttributeMaxDynamicSharedMemorySize, smem_conv);
    cudaFuncSetAttribute(k_fused<256, 8, true, 2>,
                         cudaFuncAttributeMaxDynamicSharedMemorySize, smem_dcn);

    // weight transposes (independent, tiny)
    k_transpose_dcn<<<2304, 256>>>(w_dcn, wtd);
    k_transpose_om<<<1152, 256>>>(w_om, wto);

    // offset-mask conv: om = conv3x3(x, w_om) + b_om   (raw; sigmoid applied on read)
    k_fused<128, 16, false, 3><<<1250, 256, smem_conv>>>(x, wto, nullptr, b_om, om, OMCH);

    // modulated deformable conv + ReLU
    k_fused<256, 8, true, 2><<<1250, 256, smem_dcn>>>(x, wtd, om, nullptr, out, 256);
}

// round 13
// speedup vs baseline: 1.0029x; 1.0029x over previous
#include <cuda_runtime.h>
#include <cstdint>
#include <math.h>

// Problem constants
#define HH    200
#define WW    200
#define HWSZ  40000
#define CIN   256
#define BB    2
#define CG    64      // channels per group (both real DCN groups and conv pseudo-groups)
#define NGK   36      // 4 groups * 9 taps
#define OMCH  108     // offset-mask conv output channels

// Scratch (static device arrays -- no runtime allocation)
__device__ float g_om[BB * OMCH * HWSZ];          // 34.56 MB: conv output (raw, pre-sigmoid)
__device__ float g_wt_dcn[NGK * CG * 256];        // 2.36 MB: w_dcn transposed [gk][cg][oc]
__device__ float g_wt_om[NGK * CG * 128];         // 1.18 MB: w_om transposed, oc padded to 128

typedef unsigned long long ull;

__device__ __forceinline__ ull fdup(float x) {
    ull r; asm("mov.b64 %0, {%1, %1};" : "=l"(r) : "f"(x)); return r;
}
__device__ __forceinline__ void fma2(ull& d, ull a, ull b) {
    // d = a*b + d, packed 2x fp32 (Blackwell f32x2 pipe: 2 FMA per FFMA2 issue)
    asm("fma.rn.f32x2 %0, %1, %2, %0;" : "+l"(d) : "l"(a), "l"(b));
}
__device__ __forceinline__ float2 unpk(ull a) {
    float2 r; asm("mov.b64 {%0, %1}, %2;" : "=f"(r.x), "=f"(r.y) : "l"(a)); return r;
}

// ---------------------------------------------------------------------------
// Weight transposes: [O][C][9] -> [gk][cg][oc] (oc contiguous => coalesced
// smem tile fills in the GEMM kernel).
// ---------------------------------------------------------------------------
__global__ void k_transpose_dcn(const float* __restrict__ w, float* __restrict__ wt) {
    int tid = blockIdx.x * 256 + threadIdx.x;
    if (tid >= NGK * CG * 256) return;
    int o  = tid & 255;
    int cg = (tid >> 8) & 63;
    int gk = tid >> 14;
    int g = gk / 9, k = gk - g * 9;
    wt[tid] = w[(o * CIN + g * CG + cg) * 9 + k];
}

__global__ void k_transpose_om(const float* __restrict__ w, float* __restrict__ wt) {
    int tid = blockIdx.x * 256 + threadIdx.x;
    if (tid >= NGK * CG * 128) return;
    int o  = tid & 127;
    int cg = (tid >> 7) & 63;
    int gk = tid >> 13;
    int g = gk / 9, k = gk - g * 9;
    wt[tid] = (o < OMCH) ? w[(o * CIN + g * CG + cg) * 9 + k] : 0.0f;
}

// ---------------------------------------------------------------------------
// Unified gather + GEMM kernel.
//   Tile: OCT output channels x 64 consecutive pixels (linear over B*H*W;
//         80000 % 64 == 0 and the batch boundary (40000) is tile-aligned).
//   256 threads: to = t / PIX_THR handles 8 oc (4 f32x2 pairs),
//                tp = t % PIX_THR handles PIX_PER = 64/PIX_THR pixels.
//   Per (g,k) iteration:
//     - per-pixel sampling meta in registers (pix = t & 63, 4x redundant)
//     - W tile [64 cg][OCT] -> smem (coalesced from transposed weights)
//     - gather v[64 cg][64 px] -> smem as duplicated float2 (broadcast operand
//       pre-packed => inner loop has zero mov.b64)
//     - register-tile GEMM with fma.rn.f32x2 (acc pairs along oc)
//   DEFORM=true : bilinear sample with offsets/sigmoid(mask) from g_om, ReLU.
//   DEFORM=false: identity 3x3 taps (the offset-mask conv itself), +bias.
// ---------------------------------------------------------------------------
template <int OCT, int PIX_THR, bool DEFORM, int MAXB>
__global__ void __launch_bounds__(256, MAXB)
k_fused(const float* __restrict__ x, const float* __restrict__ wt,
        const float* __restrict__ om, const float* __restrict__ bias,
        float* __restrict__ out, int o_valid)
{
    constexpr int PIX_PER = 64 / PIX_THR;
    extern __shared__ float smem[];
    float*  sWt  = smem;                           // 64 * OCT floats
    float2* vdup = (float2*)(smem + 64 * OCT);     // 64 * 64 float2 (duplicated)

    const int t   = threadIdx.x;
    const int tp  = t % PIX_THR;
    const int to  = t / PIX_THR;
    const int pix = t & 63;

    const int p0 = blockIdx.x * 64;
    const int b  = (p0 >= HWSZ) ? 1 : 0;
    const int hw = p0 - b * HWSZ + pix;
    const int h  = hw / WW;
    const int w  = hw - h * WW;

    ull acc[4][PIX_PER];
#pragma unroll
    for (int i = 0; i < 4; i++)
#pragma unroll
        for (int j = 0; j < PIX_PER; j++) acc[i][j] = 0ull;

    const int xgbase = b * CIN * HWSZ;
    const int ombase = b * OMCH * HWSZ + hw;

    for (int gk = 0; gk < NGK; gk++) {
        const int g  = gk / 9;
        const int k  = gk - g * 9;
        const int ki = k / 3;
        const int kj = k - ki * 3;

        // ---- per-pixel sampling metadata (registers) ----
        int   a00 = 0, a01 = 0, a10 = 0, a11 = 0;
        float w00, w01 = 0.f, w10 = 0.f, w11 = 0.f;
        if (DEFORM) {
            float dy = om[ombase + (g * 18 + 2 * k)     * HWSZ];
            float dx = om[ombase + (g * 18 + 2 * k + 1) * HWSZ];
            float mr = om[ombase + (72 + g * 9 + k)     * HWSZ];
            float m  = 1.0f / (1.0f + expf(-mr));
            float py = (float)(h - 1 + ki) + dy;
            float px = (float)(w - 1 + kj) + dx;
            float fy = floorf(py), fx = floorf(px);
            int   y0 = (int)fy,    x0 = (int)fx;
            float wy = py - fy,    wx = px - fx;
            bool vy0 = (unsigned)y0       < HH, vy1 = (unsigned)(y0 + 1) < HH;
            bool vx0 = (unsigned)x0       < WW, vx1 = (unsigned)(x0 + 1) < WW;
            float oy = 1.0f - wy, ox = 1.0f - wx;
            w00 = (vy0 && vx0) ? m * oy * ox : 0.0f;
            w01 = (vy0 && vx1) ? m * oy * wx : 0.0f;
            w10 = (vy1 && vx0) ? m * wy * ox : 0.0f;
            w11 = (vy1 && vx1) ? m * wy * wx : 0.0f;
            int cy0 = min(max(y0, 0), HH - 1), cy1 = min(max(y0 + 1, 0), HH - 1);
            int cx0 = min(max(x0, 0), WW - 1), cx1 = min(max(x0 + 1, 0), WW - 1);
            a00 = cy0 * WW + cx0; a01 = cy0 * WW + cx1;
            a10 = cy1 * WW + cx0; a11 = cy1 * WW + cx1;
        } else {
            int y0 = h - 1 + ki, x0 = w - 1 + kj;
            bool inb = ((unsigned)y0 < HH) && ((unsigned)x0 < WW);
            w00 = inb ? 1.0f : 0.0f;
            a00 = min(max(y0, 0), HH - 1) * WW + min(max(x0, 0), WW - 1);
        }

        // ---- W tile -> smem (coalesced float4) ----
        {
            const float4* src = (const float4*)(wt + gk * 64 * OCT);
            float4*       dst = (float4*)sWt;
#pragma unroll
            for (int j = 0; j < (64 * OCT) / (4 * 256); j++)
                dst[t + j * 256] = src[t + j * 256];
        }

        // ---- gather v[cg][pix] (thread owns fixed pix, strides cg by 4) ----
        {
            const float* pl = x + xgbase + (g * CG + (t >> 6)) * HWSZ;
#pragma unroll
            for (int e = 0; e < 16; e++) {
                float val;
                if (DEFORM) {
                    val = w00 * pl[a00] + w01 * pl[a01]
                        + w10 * pl[a10] + w11 * pl[a11];
                } else {
                    val = w00 * pl[a00];
                }
                vdup[((t >> 6) + 4 * e) * 64 + pix] = make_float2(val, val);
                pl += 4 * HWSZ;
            }
        }
        __syncthreads();

        // ---- register-tile GEMM: out[8 oc][PIX_PER px] += W[.][cg] * v[cg][.] ----
#pragma unroll 4
        for (int cg = 0; cg < 64; cg++) {
            const ulonglong2* wr = (const ulonglong2*)(sWt + cg * OCT + to * 8);
            ulonglong2 wa = wr[0];
            ulonglong2 wb = wr[1];
            const ulonglong2* vr = (const ulonglong2*)(vdup + cg * 64 + tp * PIX_PER);
#pragma unroll
            for (int q = 0; q < PIX_PER / 2; q++) {
                ulonglong2 vv = vr[q];
                fma2(acc[0][2 * q],     wa.x, vv.x);
                fma2(acc[0][2 * q + 1], wa.x, vv.y);
                fma2(acc[1][2 * q],     wa.y, vv.x);
                fma2(acc[1][2 * q + 1], wa.y, vv.y);
                fma2(acc[2][2 * q],     wb.x, vv.x);
                fma2(acc[2][2 * q + 1], wb.x, vv.y);
                fma2(acc[3][2 * q],     wb.y, vv.x);
                fma2(acc[3][2 * q + 1], wb.y, vv.y);
            }
        }
        __syncthreads();
    }

    // ---- epilogue: unpack f32x2, bias/ReLU, vectorized coalesced stores ----
    const int hwS = (p0 - b * HWSZ) + tp * PIX_PER;
#pragma unroll
    for (int pi = 0; pi < 4; pi++) {
        float v0[PIX_PER], v1[PIX_PER];
#pragma unroll
        for (int j = 0; j < PIX_PER; j++) {
            float2 u = unpk(acc[pi][j]);
            v0[j] = u.x; v1[j] = u.y;
        }
#pragma unroll
        for (int half = 0; half < 2; half++) {
            int o = to * 8 + pi * 2 + half;
            if (o < o_valid) {
                float bv = 0.0f;
                if (!DEFORM) bv = bias[o];
                float* op = out + (size_t)(b * o_valid + o) * HWSZ + hwS;
                const float* vv = half ? v1 : v0;
#pragma unroll
                for (int q = 0; q < PIX_PER / 4; q++) {
                    float4 r;
                    r.x = vv[4 * q + 0] + bv;
                    r.y = vv[4 * q + 1] + bv;
                    r.z = vv[4 * q + 2] + bv;
                    r.w = vv[4 * q + 3] + bv;
                    if (DEFORM) {
                        r.x = fmaxf(r.x, 0.0f); r.y = fmaxf(r.y, 0.0f);
                        r.z = fmaxf(r.z, 0.0f); r.w = fmaxf(r.w, 0.0f);
                    }
                    ((float4*)op)[q] = r;
                }
            }
        }
    }
}

// ---------------------------------------------------------------------------
extern "C" void kernel_launch(void* const* d_in, const int* in_sizes, int n_in,
                              void* d_out, int out_size)
{
    const float* x     = (const float*)d_in[0];   // [2,256,200,200]
    const float* w_om  = (const float*)d_in[1];   // [108,256,3,3]
    const float* b_om  = (const float*)d_in[2];   // [108]
    const float* w_dcn = (const float*)d_in[3];   // [256,256,3,3]
    float* out = (float*)d_out;                   // [2,256,200,200]

    float *om, *wtd, *wto;
    cudaGetSymbolAddress((void**)&om,  g_om);
    cudaGetSymbolAddress((void**)&wtd, g_wt_dcn);
    cudaGetSymbolAddress((void**)&wto, g_wt_om);

    const int smem_conv = 64 * 128 * 4 + 64 * 64 * 8;   // 65536
    const int smem_dcn  = 64 * 256 * 4 + 64 * 64 * 8;   // 98304
    cudaFuncSetAttribute(k_fused<128, 16, false, 3>,
                         cudaFuncAttributeMaxDynamicSharedMemorySize, smem_conv);
    cudaFuncSetAttribute(k_fused<256, 8, true, 2>,
                         cudaFuncAttributeMaxDynamicSharedMemorySize, smem_dcn);

    // weight transposes (independent, tiny)
    k_transpose_dcn<<<2304, 256>>>(w_dcn, wtd);
    k_transpose_om<<<1152, 256>>>(w_om, wto);

    // offset-mask conv: om = conv3x3(x, w_om) + b_om   (raw; sigmoid applied on read)
    k_fused<128, 16, false, 3><<<1250, 256, smem_conv>>>(x, wto, nullptr, b_om, om, OMCH);

    // modulated deformable conv + ReLU
    k_fused<256, 8, true, 2><<<1250, 256, smem_dcn>>>(x, wtd, om, nullptr, out, 256);
}

// round 14
// speedup vs baseline: 2.5737x; 2.5663x over previous
#include <cuda_runtime.h>
#include <cstdint>
#include <math.h>

// Problem constants
#define HH    200
#define WW    200
#define HWSZ  40000
#define CIN   256
#define BB    2
#define CG    64      // channels per group
#define NGK   36      // 4 groups * 9 taps
#define OMCH  108     // offset-mask conv output channels

// Scratch (static device arrays -- no runtime allocation)
__device__ float g_om[BB * OMCH * HWSZ];          // conv output (raw, pre-sigmoid)
__device__ float g_wt_dcn[NGK * CG * 256];        // w_dcn transposed [gk][cg][oc]
__device__ float g_wt_om[NGK * CG * 128];         // w_om transposed, oc padded to 128

typedef unsigned long long ull;

__device__ __forceinline__ ull fdup(float x) {
    ull r; asm("mov.b64 %0, {%1, %1};" : "=l"(r) : "f"(x)); return r;
}
__device__ __forceinline__ void fma2(ull& d, ull a, ull b) {
    asm("fma.rn.f32x2 %0, %1, %2, %0;" : "+l"(d) : "l"(a), "l"(b));
}
__device__ __forceinline__ float2 unpk(ull a) {
    float2 r; asm("mov.b64 {%0, %1}, %2;" : "=f"(r.x), "=f"(r.y) : "l"(a)); return r;
}

// ---------------------------------------------------------------------------
// Weight transposes: [O][C][9] -> [gk][cg][oc]
// ---------------------------------------------------------------------------
__global__ void k_transpose_dcn(const float* __restrict__ w, float* __restrict__ wt) {
    int tid = blockIdx.x * 256 + threadIdx.x;
    if (tid >= NGK * CG * 256) return;
    int o  = tid & 255;
    int cg = (tid >> 8) & 63;
    int gk = tid >> 14;
    int g = gk / 9, k = gk - g * 9;
    wt[tid] = w[(o * CIN + g * CG + cg) * 9 + k];
}

__global__ void k_transpose_om(const float* __restrict__ w, float* __restrict__ wt) {
    int tid = blockIdx.x * 256 + threadIdx.x;
    if (tid >= NGK * CG * 128) return;
    int o  = tid & 127;
    int cg = (tid >> 7) & 63;
    int gk = tid >> 13;
    int g = gk / 9, k = gk - g * 9;
    wt[tid] = (o < OMCH) ? w[(o * CIN + g * CG + cg) * 9 + k] : 0.0f;
}

// ---------------------------------------------------------------------------
// Gather + register-tile GEMM.
//   Block tile: OCT oc x 64 consecutive pixels. 256 threads.
//   GEMM mapping: oc_g = t>>4 (16 groups, OCT/16 oc each), px_g = t&15 (4 px).
//     Warp = 2 oc-groups x 16 px-groups:
//       - W LDS: 1-2 distinct addresses per warp -> broadcast (near-free).
//       - v LDS: 1x LDS.128 of 4 contiguous px, plain floats, conflict-free.
//     Per cg per thread: P/2 x LDS.128 (W pairs, natural layout, no movs)
//       + 1 x LDS.128 (v) + 4 fdup movs + 4*P FFMA2  ->  ~2 B LDS / FFMA2.
//   Gather mapping: pix = t&63, cg base = t>>6; v stored PLAIN (no dup).
// ---------------------------------------------------------------------------
template <int OCT, bool DEFORM, int MAXB>
__global__ void __launch_bounds__(256, MAXB)
k_fused(const float* __restrict__ x, const float* __restrict__ wt,
        const float* __restrict__ om, const float* __restrict__ bias,
        float* __restrict__ out, int o_valid)
{
    constexpr int P = OCT / 32;        // oc-pairs per thread (8 dcn, 4 conv)
    extern __shared__ float smem[];
    float* sW = smem;                  // 64 * OCT floats  [cg][oc]
    float* sV = smem + 64 * OCT;       // 64 * 64 floats   [cg][px]

    const int t    = threadIdx.x;
    const int oc_g = t >> 4;           // 0..15
    const int px_g = t & 15;           // 0..15
    const int pix  = t & 63;           // gather pixel
    const int cgb  = t >> 6;           // gather cg base (0..3)

    const int p0 = blockIdx.x * 64;
    const int b  = (p0 >= HWSZ) ? 1 : 0;
    const int hw = p0 - b * HWSZ + pix;
    const int h  = hw / WW;
    const int w  = hw - h * WW;

    ull acc[P][4];
#pragma unroll
    for (int i = 0; i < P; i++)
#pragma unroll
        for (int j = 0; j < 4; j++) acc[i][j] = 0ull;

    const int xgbase = b * CIN * HWSZ;
    const int ombase = b * OMCH * HWSZ + hw;

    for (int gk = 0; gk < NGK; gk++) {
        const int g  = gk / 9;
        const int k  = gk - g * 9;
        const int ki = k / 3;
        const int kj = k - ki * 3;

        // ---- per-pixel sampling metadata (registers, before the barrier) ----
        int   a00 = 0, a01 = 0, a10 = 0, a11 = 0;
        float w00, w01 = 0.f, w10 = 0.f, w11 = 0.f;
        if (DEFORM) {
            float dy = om[ombase + (g * 18 + 2 * k)     * HWSZ];
            float dx = om[ombase + (g * 18 + 2 * k + 1) * HWSZ];
            float mr = om[ombase + (72 + g * 9 + k)     * HWSZ];
            float m  = 1.0f / (1.0f + expf(-mr));
            float py = (float)(h - 1 + ki) + dy;
            float px = (float)(w - 1 + kj) + dx;
            float fy = floorf(py), fx = floorf(px);
            int   y0 = (int)fy,    x0 = (int)fx;
            float wy = py - fy,    wx = px - fx;
            bool vy0 = (unsigned)y0       < HH, vy1 = (unsigned)(y0 + 1) < HH;
            bool vx0 = (unsigned)x0       < WW, vx1 = (unsigned)(x0 + 1) < WW;
            float oy = 1.0f - wy, ox = 1.0f - wx;
            w00 = (vy0 && vx0) ? m * oy * ox : 0.0f;
            w01 = (vy0 && vx1) ? m * oy * wx : 0.0f;
            w10 = (vy1 && vx0) ? m * wy * ox : 0.0f;
            w11 = (vy1 && vx1) ? m * wy * wx : 0.0f;
            int cy0 = min(max(y0, 0), HH - 1), cy1 = min(max(y0 + 1, 0), HH - 1);
            int cx0 = min(max(x0, 0), WW - 1), cx1 = min(max(x0 + 1, 0), WW - 1);
            a00 = cy0 * WW + cx0; a01 = cy0 * WW + cx1;
            a10 = cy1 * WW + cx0; a11 = cy1 * WW + cx1;
        } else {
            int y0 = h - 1 + ki, x0 = w - 1 + kj;
            bool inb = ((unsigned)y0 < HH) && ((unsigned)x0 < WW);
            w00 = inb ? 1.0f : 0.0f;
            a00 = min(max(y0, 0), HH - 1) * WW + min(max(x0, 0), WW - 1);
        }

        __syncthreads();   // previous GEMM done reading sW/sV

        // ---- W tile -> smem (coalesced float4, natural [cg][oc] layout) ----
        {
            const float4* src = (const float4*)(wt + gk * 64 * OCT);
            float4*       dst = (float4*)sW;
#pragma unroll 4
            for (int j = 0; j < (64 * OCT) / (4 * 256); j++)
                dst[t + j * 256] = src[t + j * 256];
        }

        // ---- gather v[cg][pix] plain floats (conflict-free STS rows) ----
        {
            const float* pl = x + xgbase + (g * CG + cgb) * HWSZ;
#pragma unroll
            for (int e = 0; e < 16; e++) {
                float val;
                if (DEFORM) {
                    val = w00 * pl[a00] + w01 * pl[a01]
                        + w10 * pl[a10] + w11 * pl[a11];
                } else {
                    val = w00 * pl[a00];
                }
                sV[(cgb + 4 * e) * 64 + pix] = val;
                pl += 4 * HWSZ;
            }
        }
        __syncthreads();

        // ---- register-tile GEMM: acc[oc-pair][px] += W[cg][oc-pair] * v[cg][px] ----
#pragma unroll 2
        for (int cg = 0; cg < 64; cg++) {
            float4 vf = *(const float4*)(sV + cg * 64 + px_g * 4);
            ull v0 = fdup(vf.x), v1 = fdup(vf.y), v2 = fdup(vf.z), v3 = fdup(vf.w);
            const ulonglong2* wr = (const ulonglong2*)(sW + cg * OCT + oc_g * (2 * P));
#pragma unroll
            for (int pp = 0; pp < P / 2; pp++) {
                ulonglong2 w2 = wr[pp];
                fma2(acc[2 * pp][0],     w2.x, v0);
                fma2(acc[2 * pp][1],     w2.x, v1);
                fma2(acc[2 * pp][2],     w2.x, v2);
                fma2(acc[2 * pp][3],     w2.x, v3);
                fma2(acc[2 * pp + 1][0], w2.y, v0);
                fma2(acc[2 * pp + 1][1], w2.y, v1);
                fma2(acc[2 * pp + 1][2], w2.y, v2);
                fma2(acc[2 * pp + 1][3], w2.y, v3);
            }
        }
    }

    // ---- epilogue: unpack pairs, bias/ReLU, float4 stores along px ----
    const int hwS = (p0 - b * HWSZ) + px_g * 4;
#pragma unroll
    for (int p = 0; p < P; p++) {
        float2 u0 = unpk(acc[p][0]);
        float2 u1 = unpk(acc[p][1]);
        float2 u2 = unpk(acc[p][2]);
        float2 u3 = unpk(acc[p][3]);
        int ob = oc_g * (2 * P) + 2 * p;
#pragma unroll
        for (int half = 0; half < 2; half++) {
            int o = ob + half;
            if (o < o_valid) {
                float bv = DEFORM ? 0.0f : bias[o];
                float4 r;
                if (half) { r.x = u0.y + bv; r.y = u1.y + bv; r.z = u2.y + bv; r.w = u3.y + bv; }
                else      { r.x = u0.x + bv; r.y = u1.x + bv; r.z = u2.x + bv; r.w = u3.x + bv; }
                if (DEFORM) {
                    r.x = fmaxf(r.x, 0.0f); r.y = fmaxf(r.y, 0.0f);
                    r.z = fmaxf(r.z, 0.0f); r.w = fmaxf(r.w, 0.0f);
                }
                *(float4*)(out + (size_t)(b * o_valid + o) * HWSZ + hwS) = r;
            }
        }
    }
}

// ---------------------------------------------------------------------------
extern "C" void kernel_launch(void* const* d_in, const int* in_sizes, int n_in,
                              void* d_out, int out_size)
{
    const float* x     = (const float*)d_in[0];   // [2,256,200,200]
    const float* w_om  = (const float*)d_in[1];   // [108,256,3,3]
    const float* b_om  = (const float*)d_in[2];   // [108]
    const float* w_dcn = (const float*)d_in[3];   // [256,256,3,3]
    float* out = (float*)d_out;                   // [2,256,200,200]

    float *om, *wtd, *wto;
    cudaGetSymbolAddress((void**)&om,  g_om);
    cudaGetSymbolAddress((void**)&wtd, g_wt_dcn);
    cudaGetSymbolAddress((void**)&wto, g_wt_om);

    const int smem_conv = 64 * 128 * 4 + 64 * 64 * 4;   // 49152
    const int smem_dcn  = 64 * 256 * 4 + 64 * 64 * 4;   // 81920
    cudaFuncSetAttribute(k_fused<128, false, 3>,
                         cudaFuncAttributeMaxDynamicSharedMemorySize, smem_conv);
    cudaFuncSetAttribute(k_fused<256, true, 2>,
                         cudaFuncAttributeMaxDynamicSharedMemorySize, smem_dcn);

    // weight transposes (tiny)
    k_transpose_dcn<<<2304, 256>>>(w_dcn, wtd);
    k_transpose_om<<<1152, 256>>>(w_om, wto);

    // offset-mask conv: om = conv3x3(x, w_om) + b_om (raw; sigmoid on read)
    k_fused<128, false, 3><<<1250, 256, smem_conv>>>(x, wto, nullptr, b_om, om, OMCH);

    // modulated deformable conv + ReLU
    k_fused<256, true, 2><<<1250, 256, smem_dcn>>>(x, wtd, om, nullptr, out, 256);
}

// round 15
// speedup vs baseline: 2.5754x; 1.0006x over previous
#include <cuda_runtime.h>
#include <cstdint>
#include <math.h>

// Problem constants
#define HH    200
#define WW    200
#define HWSZ  40000
#define CIN   256
#define BB    2
#define CG    64      // channels per group
#define NGK   36      // 4 groups * 9 taps
#define OMCH  108     // offset-mask conv output channels

// Scratch (static device arrays -- no runtime allocation)
__device__ float g_om[BB * OMCH * HWSZ];          // conv output (raw, pre-sigmoid)
__device__ float g_wt_dcn[NGK * CG * 256];        // w_dcn transposed [gk][cg][oc]
__device__ float g_wt_om[NGK * CG * 128];         // w_om transposed, oc padded to 128

typedef unsigned long long ull;

__device__ __forceinline__ ull fdup(float x) {
    ull r; asm("mov.b64 %0, {%1, %1};" : "=l"(r) : "f"(x)); return r;
}
__device__ __forceinline__ void fma2(ull& d, ull a, ull b) {
    asm("fma.rn.f32x2 %0, %1, %2, %0;" : "+l"(d) : "l"(a), "l"(b));
}
__device__ __forceinline__ float2 unpk(ull a) {
    float2 r; asm("mov.b64 {%0, %1}, %2;" : "=f"(r.x), "=f"(r.y) : "l"(a)); return r;
}

// ---------------------------------------------------------------------------
// Weight transposes: [O][C][9] -> [gk][cg][oc]
// ---------------------------------------------------------------------------
__global__ void k_transpose_dcn(const float* __restrict__ w, float* __restrict__ wt) {
    int tid = blockIdx.x * 256 + threadIdx.x;
    if (tid >= NGK * CG * 256) return;
    int o  = tid & 255;
    int cg = (tid >> 8) & 63;
    int gk = tid >> 14;
    int g = gk / 9, k = gk - g * 9;
    wt[tid] = w[(o * CIN + g * CG + cg) * 9 + k];
}

__global__ void k_transpose_om(const float* __restrict__ w, float* __restrict__ wt) {
    int tid = blockIdx.x * 256 + threadIdx.x;
    if (tid >= NGK * CG * 128) return;
    int o  = tid & 127;
    int cg = (tid >> 7) & 63;
    int gk = tid >> 13;
    int g = gk / 9, k = gk - g * 9;
    wt[tid] = (o < OMCH) ? w[(o * CIN + g * CG + cg) * 9 + k] : 0.0f;
}

// ---------------------------------------------------------------------------
// Gather + register-tile GEMM.
//   Block tile: OCT oc x 64 consecutive pixels. 256 threads.
//   GEMM mapping: oc_g = t>>4 (16 groups, OCT/16 oc each), px_g = t&15 (4 px).
//     Warp = 2 oc-groups x 16 px-groups:
//       - W LDS: 1-2 distinct addresses per warp -> broadcast (near-free).
//       - v LDS: 1x LDS.128 of 4 contiguous px, plain floats, conflict-free.
//     Per cg per thread: P/2 x LDS.128 (W pairs, natural layout, no movs)
//       + 1 x LDS.128 (v) + 4 fdup movs + 4*P FFMA2  ->  ~2 B LDS / FFMA2.
//   Gather mapping: pix = t&63, cg base = t>>6; v stored PLAIN (no dup).
// ---------------------------------------------------------------------------
template <int OCT, bool DEFORM, int MAXB>
__global__ void __launch_bounds__(256, MAXB)
k_fused(const float* __restrict__ x, const float* __restrict__ wt,
        const float* __restrict__ om, const float* __restrict__ bias,
        float* __restrict__ out, int o_valid)
{
    constexpr int P = OCT / 32;        // oc-pairs per thread (8 dcn, 4 conv)
    extern __shared__ float smem[];
    float* sW = smem;                  // 64 * OCT floats  [cg][oc]
    float* sV = smem + 64 * OCT;       // 64 * 64 floats   [cg][px]

    const int t    = threadIdx.x;
    const int oc_g = t >> 4;           // 0..15
    const int px_g = t & 15;           // 0..15
    const int pix  = t & 63;           // gather pixel
    const int cgb  = t >> 6;           // gather cg base (0..3)

    const int p0 = blockIdx.x * 64;
    const int b  = (p0 >= HWSZ) ? 1 : 0;
    const int hw = p0 - b * HWSZ + pix;
    const int h  = hw / WW;
    const int w  = hw - h * WW;

    ull acc[P][4];
#pragma unroll
    for (int i = 0; i < P; i++)
#pragma unroll
        for (int j = 0; j < 4; j++) acc[i][j] = 0ull;

    const int xgbase = b * CIN * HWSZ;
    const int ombase = b * OMCH * HWSZ + hw;

    for (int gk = 0; gk < NGK; gk++) {
        const int g  = gk / 9;
        const int k  = gk - g * 9;
        const int ki = k / 3;
        const int kj = k - ki * 3;

        // ---- per-pixel sampling metadata (registers, before the barrier) ----
        int   a00 = 0, a01 = 0, a10 = 0, a11 = 0;
        float w00, w01 = 0.f, w10 = 0.f, w11 = 0.f;
        if (DEFORM) {
            float dy = om[ombase + (g * 18 + 2 * k)     * HWSZ];
            float dx = om[ombase + (g * 18 + 2 * k + 1) * HWSZ];
            float mr = om[ombase + (72 + g * 9 + k)     * HWSZ];
            float m  = 1.0f / (1.0f + expf(-mr));
            float py = (float)(h - 1 + ki) + dy;
            float px = (float)(w - 1 + kj) + dx;
            float fy = floorf(py), fx = floorf(px);
            int   y0 = (int)fy,    x0 = (int)fx;
            float wy = py - fy,    wx = px - fx;
            bool vy0 = (unsigned)y0       < HH, vy1 = (unsigned)(y0 + 1) < HH;
            bool vx0 = (unsigned)x0       < WW, vx1 = (unsigned)(x0 + 1) < WW;
            float oy = 1.0f - wy, ox = 1.0f - wx;
            w00 = (vy0 && vx0) ? m * oy * ox : 0.0f;
            w01 = (vy0 && vx1) ? m * oy * wx : 0.0f;
            w10 = (vy1 && vx0) ? m * wy * ox : 0.0f;
            w11 = (vy1 && vx1) ? m * wy * wx : 0.0f;
            int cy0 = min(max(y0, 0), HH - 1), cy1 = min(max(y0 + 1, 0), HH - 1);
            int cx0 = min(max(x0, 0), WW - 1), cx1 = min(max(x0 + 1, 0), WW - 1);
            a00 = cy0 * WW + cx0; a01 = cy0 * WW + cx1;
            a10 = cy1 * WW + cx0; a11 = cy1 * WW + cx1;
        } else {
            int y0 = h - 1 + ki, x0 = w - 1 + kj;
            bool inb = ((unsigned)y0 < HH) && ((unsigned)x0 < WW);
            w00 = inb ? 1.0f : 0.0f;
            a00 = min(max(y0, 0), HH - 1) * WW + min(max(x0, 0), WW - 1);
        }

        __syncthreads();   // previous GEMM done reading sW/sV

        // ---- W tile -> smem (coalesced float4, natural [cg][oc] layout) ----
        {
            const float4* src = (const float4*)(wt + gk * 64 * OCT);
            float4*       dst = (float4*)sW;
#pragma unroll 4
            for (int j = 0; j < (64 * OCT) / (4 * 256); j++)
                dst[t + j * 256] = src[t + j * 256];
        }

        // ---- gather v[cg][pix] plain floats (conflict-free STS rows) ----
        {
            const float* pl = x + xgbase + (g * CG + cgb) * HWSZ;
#pragma unroll
            for (int e = 0; e < 16; e++) {
                float val;
                if (DEFORM) {
                    val = w00 * pl[a00] + w01 * pl[a01]
                        + w10 * pl[a10] + w11 * pl[a11];
                } else {
                    val = w00 * pl[a00];
                }
                sV[(cgb + 4 * e) * 64 + pix] = val;
                pl += 4 * HWSZ;
            }
        }
        __syncthreads();

        // ---- register-tile GEMM: acc[oc-pair][px] += W[cg][oc-pair] * v[cg][px] ----
#pragma unroll 2
        for (int cg = 0; cg < 64; cg++) {
            float4 vf = *(const float4*)(sV + cg * 64 + px_g * 4);
            ull v0 = fdup(vf.x), v1 = fdup(vf.y), v2 = fdup(vf.z), v3 = fdup(vf.w);
            const ulonglong2* wr = (const ulonglong2*)(sW + cg * OCT + oc_g * (2 * P));
#pragma unroll
            for (int pp = 0; pp < P / 2; pp++) {
                ulonglong2 w2 = wr[pp];
                fma2(acc[2 * pp][0],     w2.x, v0);
                fma2(acc[2 * pp][1],     w2.x, v1);
                fma2(acc[2 * pp][2],     w2.x, v2);
                fma2(acc[2 * pp][3],     w2.x, v3);
                fma2(acc[2 * pp + 1][0], w2.y, v0);
                fma2(acc[2 * pp + 1][1], w2.y, v1);
                fma2(acc[2 * pp + 1][2], w2.y, v2);
                fma2(acc[2 * pp + 1][3], w2.y, v3);
            }
        }
    }

    // ---- epilogue: unpack pairs, bias/ReLU, float4 stores along px ----
    const int hwS = (p0 - b * HWSZ) + px_g * 4;
#pragma unroll
    for (int p = 0; p < P; p++) {
        float2 u0 = unpk(acc[p][0]);
        float2 u1 = unpk(acc[p][1]);
        float2 u2 = unpk(acc[p][2]);
        float2 u3 = unpk(acc[p][3]);
        int ob = oc_g * (2 * P) + 2 * p;
#pragma unroll
        for (int half = 0; half < 2; half++) {
            int o = ob + half;
            if (o < o_valid) {
                float bv = DEFORM ? 0.0f : bias[o];
                float4 r;
                if (half) { r.x = u0.y + bv; r.y = u1.y + bv; r.z = u2.y + bv; r.w = u3.y + bv; }
                else      { r.x = u0.x + bv; r.y = u1.x + bv; r.z = u2.x + bv; r.w = u3.x + bv; }
                if (DEFORM) {
                    r.x = fmaxf(r.x, 0.0f); r.y = fmaxf(r.y, 0.0f);
                    r.z = fmaxf(r.z, 0.0f); r.w = fmaxf(r.w, 0.0f);
                }
                *(float4*)(out + (size_t)(b * o_valid + o) * HWSZ + hwS) = r;
            }
        }
    }
}

// ---------------------------------------------------------------------------
extern "C" void kernel_launch(void* const* d_in, const int* in_sizes, int n_in,
                              void* d_out, int out_size)
{
    const float* x     = (const float*)d_in[0];   // [2,256,200,200]
    const float* w_om  = (const float*)d_in[1];   // [108,256,3,3]
    const float* b_om  = (const float*)d_in[2];   // [108]
    const float* w_dcn = (const float*)d_in[3];   // [256,256,3,3]
    float* out = (float*)d_out;                   // [2,256,200,200]

    float *om, *wtd, *wto;
    cudaGetSymbolAddress((void**)&om,  g_om);
    cudaGetSymbolAddress((void**)&wtd, g_wt_dcn);
    cudaGetSymbolAddress((void**)&wto, g_wt_om);

    const int smem_conv = 64 * 128 * 4 + 64 * 64 * 4;   // 49152
    const int smem_dcn  = 64 * 256 * 4 + 64 * 64 * 4;   // 81920
    cudaFuncSetAttribute(k_fused<128, false, 3>,
                         cudaFuncAttributeMaxDynamicSharedMemorySize, smem_conv);
    cudaFuncSetAttribute(k_fused<256, true, 2>,
                         cudaFuncAttributeMaxDynamicSharedMemorySize, smem_dcn);

    // weight transposes (tiny)
    k_transpose_dcn<<<2304, 256>>>(w_dcn, wtd);
    k_transpose_om<<<1152, 256>>>(w_om, wto);

    // offset-mask conv: om = conv3x3(x, w_om) + b_om (raw; sigmoid on read)
    k_fused<128, false, 3><<<1250, 256, smem_conv>>>(x, wto, nullptr, b_om, om, OMCH);

    // modulated deformable conv + ReLU
    k_fused<256, true, 2><<<1250, 256, smem_dcn>>>(x, wtd, om, nullptr, out, 256);
}

// round 16
// speedup vs baseline: 2.5762x; 1.0003x over previous
#include <cuda_runtime.h>
#include <cstdint>
#include <math.h>

// Problem constants
#define HH    200
#define WW    200
#define HWSZ  40000
#define CIN   256
#define BB    2
#define CG    64      // channels per group
#define NGK   36      // 4 groups * 9 taps
#define OMCH  108     // offset-mask conv output channels

// Scratch (static device arrays -- no runtime allocation)
__device__ float g_om[BB * OMCH * HWSZ];          // conv output (raw, pre-sigmoid)
__device__ float g_wt_dcn[NGK * CG * 256];        // w_dcn transposed [gk][cg][oc]
__device__ float g_wt_om[NGK * CG * 128];         // w_om transposed, oc padded to 128

typedef unsigned long long ull;

__device__ __forceinline__ ull fdup(float x) {
    ull r; asm("mov.b64 %0, {%1, %1};" : "=l"(r) : "f"(x)); return r;
}
__device__ __forceinline__ void fma2(ull& d, ull a, ull b) {
    asm("fma.rn.f32x2 %0, %1, %2, %0;" : "+l"(d) : "l"(a), "l"(b));
}
__device__ __forceinline__ float2 unpk(ull a) {
    float2 r; asm("mov.b64 {%0, %1}, %2;" : "=f"(r.x), "=f"(r.y) : "l"(a)); return r;
}

// ---------------------------------------------------------------------------
// Weight transposes: [O][C][9] -> [gk][cg][oc]
// ---------------------------------------------------------------------------
__global__ void k_transpose_dcn(const float* __restrict__ w, float* __restrict__ wt) {
    int tid = blockIdx.x * 256 + threadIdx.x;
    if (tid >= NGK * CG * 256) return;
    int o  = tid & 255;
    int cg = (tid >> 8) & 63;
    int gk = tid >> 14;
    int g = gk / 9, k = gk - g * 9;
    wt[tid] = w[(o * CIN + g * CG + cg) * 9 + k];
}

__global__ void k_transpose_om(const float* __restrict__ w, float* __restrict__ wt) {
    int tid = blockIdx.x * 256 + threadIdx.x;
    if (tid >= NGK * CG * 128) return;
    int o  = tid & 127;
    int cg = (tid >> 7) & 63;
    int gk = tid >> 13;
    int g = gk / 9, k = gk - g * 9;
    wt[tid] = (o < OMCH) ? w[(o * CIN + g * CG + cg) * 9 + k] : 0.0f;
}

// ---------------------------------------------------------------------------
// Gather + register-tile GEMM.
//   Block tile: OCT oc x 64 consecutive pixels. 256 threads.
//   GEMM mapping: oc_g = t>>4 (16 groups, OCT/16 oc each), px_g = t&15 (4 px).
//     Warp = 2 oc-groups x 16 px-groups:
//       - W LDS: 1-2 distinct addresses per warp -> broadcast (near-free).
//       - v LDS: 1x LDS.128 of 4 contiguous px, plain floats, conflict-free.
//     Per cg per thread: P/2 x LDS.128 (W pairs, natural layout, no movs)
//       + 1 x LDS.128 (v) + 4 fdup movs + 4*P FFMA2  ->  ~2 B LDS / FFMA2.
//   Gather mapping: pix = t&63, cg base = t>>6; v stored PLAIN (no dup).
// ---------------------------------------------------------------------------
template <int OCT, bool DEFORM, int MAXB>
__global__ void __launch_bounds__(256, MAXB)
k_fused(const float* __restrict__ x, const float* __restrict__ wt,
        const float* __restrict__ om, const float* __restrict__ bias,
        float* __restrict__ out, int o_valid)
{
    constexpr int P = OCT / 32;        // oc-pairs per thread (8 dcn, 4 conv)
    extern __shared__ float smem[];
    float* sW = smem;                  // 64 * OCT floats  [cg][oc]
    float* sV = smem + 64 * OCT;       // 64 * 64 floats   [cg][px]

    const int t    = threadIdx.x;
    const int oc_g = t >> 4;           // 0..15
    const int px_g = t & 15;           // 0..15
    const int pix  = t & 63;           // gather pixel
    const int cgb  = t >> 6;           // gather cg base (0..3)

    const int p0 = blockIdx.x * 64;
    const int b  = (p0 >= HWSZ) ? 1 : 0;
    const int hw = p0 - b * HWSZ + pix;
    const int h  = hw / WW;
    const int w  = hw - h * WW;

    ull acc[P][4];
#pragma unroll
    for (int i = 0; i < P; i++)
#pragma unroll
        for (int j = 0; j < 4; j++) acc[i][j] = 0ull;

    const int xgbase = b * CIN * HWSZ;
    const int ombase = b * OMCH * HWSZ + hw;

    for (int gk = 0; gk < NGK; gk++) {
        const int g  = gk / 9;
        const int k  = gk - g * 9;
        const int ki = k / 3;
        const int kj = k - ki * 3;

        // ---- per-pixel sampling metadata (registers, before the barrier) ----
        int   a00 = 0, a01 = 0, a10 = 0, a11 = 0;
        float w00, w01 = 0.f, w10 = 0.f, w11 = 0.f;
        if (DEFORM) {
            float dy = om[ombase + (g * 18 + 2 * k)     * HWSZ];
            float dx = om[ombase + (g * 18 + 2 * k + 1) * HWSZ];
            float mr = om[ombase + (72 + g * 9 + k)     * HWSZ];
            float m  = 1.0f / (1.0f + expf(-mr));
            float py = (float)(h - 1 + ki) + dy;
            float px = (float)(w - 1 + kj) + dx;
            float fy = floorf(py), fx = floorf(px);
            int   y0 = (int)fy,    x0 = (int)fx;
            float wy = py - fy,    wx = px - fx;
            bool vy0 = (unsigned)y0       < HH, vy1 = (unsigned)(y0 + 1) < HH;
            bool vx0 = (unsigned)x0       < WW, vx1 = (unsigned)(x0 + 1) < WW;
            float oy = 1.0f - wy, ox = 1.0f - wx;
            w00 = (vy0 && vx0) ? m * oy * ox : 0.0f;
            w01 = (vy0 && vx1) ? m * oy * wx : 0.0f;
            w10 = (vy1 && vx0) ? m * wy * ox : 0.0f;
            w11 = (vy1 && vx1) ? m * wy * wx : 0.0f;
            int cy0 = min(max(y0, 0), HH - 1), cy1 = min(max(y0 + 1, 0), HH - 1);
            int cx0 = min(max(x0, 0), WW - 1), cx1 = min(max(x0 + 1, 0), WW - 1);
            a00 = cy0 * WW + cx0; a01 = cy0 * WW + cx1;
            a10 = cy1 * WW + cx0; a11 = cy1 * WW + cx1;
        } else {
            int y0 = h - 1 + ki, x0 = w - 1 + kj;
            bool inb = ((unsigned)y0 < HH) && ((unsigned)x0 < WW);
            w00 = inb ? 1.0f : 0.0f;
            a00 = min(max(y0, 0), HH - 1) * WW + min(max(x0, 0), WW - 1);
        }

        __syncthreads();   // previous GEMM done reading sW/sV

        // ---- W tile -> smem (coalesced float4, natural [cg][oc] layout) ----
        {
            const float4* src = (const float4*)(wt + gk * 64 * OCT);
            float4*       dst = (float4*)sW;
#pragma unroll 4
            for (int j = 0; j < (64 * OCT) / (4 * 256); j++)
                dst[t + j * 256] = src[t + j * 256];
        }

        // ---- gather v[cg][pix] plain floats (conflict-free STS rows) ----
        {
            const float* pl = x + xgbase + (g * CG + cgb) * HWSZ;
#pragma unroll
            for (int e = 0; e < 16; e++) {
                float val;
                if (DEFORM) {
                    val = w00 * pl[a00] + w01 * pl[a01]
                        + w10 * pl[a10] + w11 * pl[a11];
                } else {
                    val = w00 * pl[a00];
                }
                sV[(cgb + 4 * e) * 64 + pix] = val;
                pl += 4 * HWSZ;
            }
        }
        __syncthreads();

        // ---- register-tile GEMM: acc[oc-pair][px] += W[cg][oc-pair] * v[cg][px] ----
#pragma unroll 2
        for (int cg = 0; cg < 64; cg++) {
            float4 vf = *(const float4*)(sV + cg * 64 + px_g * 4);
            ull v0 = fdup(vf.x), v1 = fdup(vf.y), v2 = fdup(vf.z), v3 = fdup(vf.w);
            const ulonglong2* wr = (const ulonglong2*)(sW + cg * OCT + oc_g * (2 * P));
#pragma unroll
            for (int pp = 0; pp < P / 2; pp++) {
                ulonglong2 w2 = wr[pp];
                fma2(acc[2 * pp][0],     w2.x, v0);
                fma2(acc[2 * pp][1],     w2.x, v1);
                fma2(acc[2 * pp][2],     w2.x, v2);
                fma2(acc[2 * pp][3],     w2.x, v3);
                fma2(acc[2 * pp + 1][0], w2.y, v0);
                fma2(acc[2 * pp + 1][1], w2.y, v1);
                fma2(acc[2 * pp + 1][2], w2.y, v2);
                fma2(acc[2 * pp + 1][3], w2.y, v3);
            }
        }
    }

    // ---- epilogue: unpack pairs, bias/ReLU, float4 stores along px ----
    const int hwS = (p0 - b * HWSZ) + px_g * 4;
#pragma unroll
    for (int p = 0; p < P; p++) {
        float2 u0 = unpk(acc[p][0]);
        float2 u1 = unpk(acc[p][1]);
        float2 u2 = unpk(acc[p][2]);
        float2 u3 = unpk(acc[p][3]);
        int ob = oc_g * (2 * P) + 2 * p;
#pragma unroll
        for (int half = 0; half < 2; half++) {
            int o = ob + half;
            if (o < o_valid) {
                float bv = DEFORM ? 0.0f : bias[o];
                float4 r;
                if (half) { r.x = u0.y + bv; r.y = u1.y + bv; r.z = u2.y + bv; r.w = u3.y + bv; }
                else      { r.x = u0.x + bv; r.y = u1.x + bv; r.z = u2.x + bv; r.w = u3.x + bv; }
                if (DEFORM) {
                    r.x = fmaxf(r.x, 0.0f); r.y = fmaxf(r.y, 0.0f);
                    r.z = fmaxf(r.z, 0.0f); r.w = fmaxf(r.w, 0.0f);
                }
                *(float4*)(out + (size_t)(b * o_valid + o) * HWSZ + hwS) = r;
            }
        }
    }
}

// ---------------------------------------------------------------------------
extern "C" void kernel_launch(void* const* d_in, const int* in_sizes, int n_in,
                              void* d_out, int out_size)
{
    const float* x     = (const float*)d_in[0];   // [2,256,200,200]
    const float* w_om  = (const float*)d_in[1];   // [108,256,3,3]
    const float* b_om  = (const float*)d_in[2];   // [108]
    const float* w_dcn = (const float*)d_in[3];   // [256,256,3,3]
    float* out = (float*)d_out;                   // [2,256,200,200]

    float *om, *wtd, *wto;
    cudaGetSymbolAddress((void**)&om,  g_om);
    cudaGetSymbolAddress((void**)&wtd, g_wt_dcn);
    cudaGetSymbolAddress((void**)&wto, g_wt_om);

    const int smem_conv = 64 * 128 * 4 + 64 * 64 * 4;   // 49152
    const int smem_dcn  = 64 * 256 * 4 + 64 * 64 * 4;   // 81920
    cudaFuncSetAttribute(k_fused<128, false, 3>,
                         cudaFuncAttributeMaxDynamicSharedMemorySize, smem_conv);
    cudaFuncSetAttribute(k_fused<256, true, 2>,
                         cudaFuncAttributeMaxDynamicSharedMemorySize, smem_dcn);

    // weight transposes (tiny)
    k_transpose_dcn<<<2304, 256>>>(w_dcn, wtd);
    k_transpose_om<<<1152, 256>>>(w_om, wto);

    // offset-mask conv: om = conv3x3(x, w_om) + b_om (raw; sigmoid on read)
    k_fused<128, false, 3><<<1250, 256, smem_conv>>>(x, wto, nullptr, b_om, om, OMCH);

    // modulated deformable conv + ReLU
    k_fused<256, true, 2><<<1250, 256, smem_dcn>>>(x, wtd, om, nullptr, out, 256);
}

// round 17
// speedup vs baseline: 2.7284x; 1.0591x over previous
#include <cuda_runtime.h>
#include <cstdint>
#include <math.h>

// Problem constants
#define HH    200
#define WW    200
#define HWSZ  40000
#define CIN   256
#define BB    2
#define CG    64      // channels per group
#define NGK   36      // 4 groups * 9 taps
#define OMCH  108     // offset-mask conv output channels

// Scratch (static device arrays -- no runtime allocation)
__device__ float g_om[BB * OMCH * HWSZ];          // conv output (raw, pre-sigmoid)
__device__ float g_wt_dcn[NGK * CG * 256];        // w_dcn transposed [gk][cg][oc]
__device__ float g_wt_om[NGK * CG * 128];         // w_om transposed, oc padded to 128

typedef unsigned long long ull;

__device__ __forceinline__ ull fdup(float x) {
    ull r; asm("mov.b64 %0, {%1, %1};" : "=l"(r) : "f"(x)); return r;
}
__device__ __forceinline__ void fma2(ull& d, ull a, ull b) {
    asm("fma.rn.f32x2 %0, %1, %2, %0;" : "+l"(d) : "l"(a), "l"(b));
}
__device__ __forceinline__ float2 unpk(ull a) {
    float2 r; asm("mov.b64 {%0, %1}, %2;" : "=f"(r.x), "=f"(r.y) : "l"(a)); return r;
}

// ---------------------------------------------------------------------------
// Weight transposes: [O][C][9] -> [gk][cg][oc]
// ---------------------------------------------------------------------------
__global__ void k_transpose_dcn(const float* __restrict__ w, float* __restrict__ wt) {
    int tid = blockIdx.x * 256 + threadIdx.x;
    if (tid >= NGK * CG * 256) return;
    int o  = tid & 255;
    int cg = (tid >> 8) & 63;
    int gk = tid >> 14;
    int g = gk / 9, k = gk - g * 9;
    wt[tid] = w[(o * CIN + g * CG + cg) * 9 + k];
}

__global__ void k_transpose_om(const float* __restrict__ w, float* __restrict__ wt) {
    int tid = blockIdx.x * 256 + threadIdx.x;
    if (tid >= NGK * CG * 128) return;
    int o  = tid & 127;
    int cg = (tid >> 7) & 63;
    int gk = tid >> 13;
    int g = gk / 9, k = gk - g * 9;
    wt[tid] = (o < OMCH) ? w[(o * CIN + g * CG + cg) * 9 + k] : 0.0f;
}

// ---------------------------------------------------------------------------
// Gather + register-tile GEMM, software-pipelined:
//   - sV double-buffered: the gather for gk+1 is interleaved into the GEMM of
//     gk (LDGs at cg%4==0, combine+STS at cg%4==2) so scattered-load latency
//     hides under FFMA2 issue instead of serializing in its own phase.
//   - sW single-buffered: filled in a short barrier window per gk (bulk copy,
//     MLP=16, cheap).
//   GEMM mapping unchanged from R16: oc_g = t>>4 (16 groups x 2P oc),
//   px_g = t&15 (4 px); warp = 2 oc-groups -> W LDS is broadcast.
// ---------------------------------------------------------------------------
template <int OCT, bool DEFORM, int MAXB>
__global__ void __launch_bounds__(256, MAXB)
k_fused(const float* __restrict__ x, const float* __restrict__ wt,
        const float* __restrict__ om, const float* __restrict__ bias,
        float* __restrict__ out, int o_valid)
{
    constexpr int P = OCT / 32;        // oc-pairs per thread (8 dcn, 4 conv)
    extern __shared__ float smem[];
    float* sW  = smem;                 // 64 * OCT floats  [cg][oc]
    float* sV0 = smem + 64 * OCT;      // 2 x 64*64 floats [cg][px] (double buffer)

    const int t    = threadIdx.x;
    const int oc_g = t >> 4;           // 0..15
    const int px_g = t & 15;           // 0..15
    const int pix  = t & 63;           // gather pixel
    const int cgb  = t >> 6;           // gather cg base (0..3)

    const int p0 = blockIdx.x * 64;
    const int b  = (p0 >= HWSZ) ? 1 : 0;
    const int hw = p0 - b * HWSZ + pix;
    const int h  = hw / WW;
    const int w  = hw - h * WW;

    ull acc[P][4];
#pragma unroll
    for (int i = 0; i < P; i++)
#pragma unroll
        for (int j = 0; j < 4; j++) acc[i][j] = 0ull;

    const int xgbase = b * CIN * HWSZ;
    const int ombase = b * OMCH * HWSZ + hw;

    // per-pixel sampling metadata for tap gk
    auto meta = [&](int gk, float& w00, float& w01, float& w10, float& w11,
                    int& a00, int& a01, int& a10, int& a11) {
        int g = gk / 9, k = gk - g * 9;
        int ki = k / 3, kj = k - ki * 3;
        if constexpr (DEFORM) {
            float dy = om[ombase + (g * 18 + 2 * k)     * HWSZ];
            float dx = om[ombase + (g * 18 + 2 * k + 1) * HWSZ];
            float mr = om[ombase + (72 + g * 9 + k)     * HWSZ];
            float m  = 1.0f / (1.0f + __expf(-mr));
            float py = (float)(h - 1 + ki) + dy;
            float px = (float)(w - 1 + kj) + dx;
            float fy = floorf(py), fx = floorf(px);
            int   y0 = (int)fy,    x0 = (int)fx;
            float wy = py - fy,    wx = px - fx;
            bool vy0 = (unsigned)y0       < HH, vy1 = (unsigned)(y0 + 1) < HH;
            bool vx0 = (unsigned)x0       < WW, vx1 = (unsigned)(x0 + 1) < WW;
            float oy = 1.0f - wy, ox = 1.0f - wx;
            w00 = (vy0 && vx0) ? m * oy * ox : 0.0f;
            w01 = (vy0 && vx1) ? m * oy * wx : 0.0f;
            w10 = (vy1 && vx0) ? m * wy * ox : 0.0f;
            w11 = (vy1 && vx1) ? m * wy * wx : 0.0f;
            int cy0 = min(max(y0, 0), HH - 1), cy1 = min(max(y0 + 1, 0), HH - 1);
            int cx0 = min(max(x0, 0), WW - 1), cx1 = min(max(x0 + 1, 0), WW - 1);
            a00 = cy0 * WW + cx0; a01 = cy0 * WW + cx1;
            a10 = cy1 * WW + cx0; a11 = cy1 * WW + cx1;
        } else {
            int y0 = h - 1 + ki, x0 = w - 1 + kj;
            bool inb = ((unsigned)y0 < HH) && ((unsigned)x0 < WW);
            w00 = inb ? 1.0f : 0.0f;
            w01 = w10 = w11 = 0.0f;
            a00 = min(max(y0, 0), HH - 1) * WW + min(max(x0, 0), WW - 1);
            a01 = a10 = a11 = a00;
        }
    };

    auto fill_W = [&](int gk) {
        const float4* src = (const float4*)(wt + gk * 64 * OCT);
        float4*       dst = (float4*)sW;
#pragma unroll
        for (int j = 0; j < (64 * OCT) / 1024; j++)
            dst[t + j * 256] = src[t + j * 256];
    };

    // ---- prologue: V(0) (blocking) + W(0) ----
    {
        float w00, w01, w10, w11; int a00, a01, a10, a11;
        meta(0, w00, w01, w10, w11, a00, a01, a10, a11);
        const float* pl = x + xgbase + cgb * HWSZ;  // gk=0 => g=0
#pragma unroll
        for (int e = 0; e < 16; e++) {
            float val;
            if constexpr (DEFORM)
                val = w00 * pl[a00] + w01 * pl[a01] + w10 * pl[a10] + w11 * pl[a11];
            else
                val = w00 * pl[a00];
            sV0[(cgb + 4 * e) * 64 + pix] = val;
            pl += 4 * HWSZ;
        }
        fill_W(0);
    }
    __syncthreads();

    // ---- main loop: GEMM(gk) with interleaved V-gather(gk+1) ----
    for (int gk = 0; gk < NGK; gk++) {
        float* sVc = sV0 + (gk & 1) * 4096;
        float* sVn = sV0 + ((gk & 1) ^ 1) * 4096;
        const bool hn = (gk + 1 < NGK);

        float nw00 = 0.f, nw01 = 0.f, nw10 = 0.f, nw11 = 0.f;
        int   na00 = 0,   na01 = 0,   na10 = 0,   na11 = 0;
        const float* xg = x + xgbase + cgb * HWSZ;
        if (hn) {
            meta(gk + 1, nw00, nw01, nw10, nw11, na00, na01, na10, na11);
            xg += ((gk + 1) / 9) * CG * HWSZ;
        }

        float s0 = 0.f, s1 = 0.f, s2 = 0.f, s3 = 0.f;
#pragma unroll 8
        for (int cg = 0; cg < 64; cg++) {
            // stage LDGs for tap-set e = cg/4 of gk+1 (channel = cgb + cg)
            if ((cg & 3) == 0 && hn) {
                const float* pl = xg + cg * HWSZ;
                s0 = pl[na00];
                if constexpr (DEFORM) { s1 = pl[na01]; s2 = pl[na10]; s3 = pl[na11]; }
            }

            // GEMM: acc[oc-pair][px] += W[cg][oc-pair] * v[cg][px]
            float4 vf = *(const float4*)(sVc + cg * 64 + px_g * 4);
            ull v0 = fdup(vf.x), v1 = fdup(vf.y), v2 = fdup(vf.z), v3 = fdup(vf.w);
            const ulonglong2* wr = (const ulonglong2*)(sW + cg * OCT + oc_g * (2 * P));
#pragma unroll
            for (int pp = 0; pp < P / 2; pp++) {
                ulonglong2 w2 = wr[pp];
                fma2(acc[2 * pp][0],     w2.x, v0);
                fma2(acc[2 * pp][1],     w2.x, v1);
                fma2(acc[2 * pp][2],     w2.x, v2);
                fma2(acc[2 * pp][3],     w2.x, v3);
                fma2(acc[2 * pp + 1][0], w2.y, v0);
                fma2(acc[2 * pp + 1][1], w2.y, v1);
                fma2(acc[2 * pp + 1][2], w2.y, v2);
                fma2(acc[2 * pp + 1][3], w2.y, v3);
            }

            // combine + STS two cg later (covers LDG latency with FFMA2)
            if ((cg & 3) == 2 && hn) {
                float val;
                if constexpr (DEFORM)
                    val = nw00 * s0 + nw01 * s1 + nw10 * s2 + nw11 * s3;
                else
                    val = nw00 * s0;
                sVn[(cgb + cg - 2) * 64 + pix] = val;
            }
        }

        if (hn) {
            __syncthreads();      // GEMM(gk) done reading sW; sVn complete
            fill_W(gk + 1);
            __syncthreads();      // sW ready for GEMM(gk+1)
        }
    }

    // ---- epilogue: unpack pairs, bias/ReLU, float4 stores along px ----
    const int hwS = (p0 - b * HWSZ) + px_g * 4;
#pragma unroll
    for (int p = 0; p < P; p++) {
        float2 u0 = unpk(acc[p][0]);
        float2 u1 = unpk(acc[p][1]);
        float2 u2 = unpk(acc[p][2]);
        float2 u3 = unpk(acc[p][3]);
        int ob = oc_g * (2 * P) + 2 * p;
#pragma unroll
        for (int half = 0; half < 2; half++) {
            int o = ob + half;
            if (o < o_valid) {
                float bv = DEFORM ? 0.0f : bias[o];
                float4 r;
                if (half) { r.x = u0.y + bv; r.y = u1.y + bv; r.z = u2.y + bv; r.w = u3.y + bv; }
                else      { r.x = u0.x + bv; r.y = u1.x + bv; r.z = u2.x + bv; r.w = u3.x + bv; }
                if (DEFORM) {
                    r.x = fmaxf(r.x, 0.0f); r.y = fmaxf(r.y, 0.0f);
                    r.z = fmaxf(r.z, 0.0f); r.w = fmaxf(r.w, 0.0f);
                }
                *(float4*)(out + (size_t)(b * o_valid + o) * HWSZ + hwS) = r;
            }
        }
    }
}

// ---------------------------------------------------------------------------
extern "C" void kernel_launch(void* const* d_in, const int* in_sizes, int n_in,
                              void* d_out, int out_size)
{
    const float* x     = (const float*)d_in[0];   // [2,256,200,200]
    const float* w_om  = (const float*)d_in[1];   // [108,256,3,3]
    const float* b_om  = (const float*)d_in[2];   // [108]
    const float* w_dcn = (const float*)d_in[3];   // [256,256,3,3]
    float* out = (float*)d_out;                   // [2,256,200,200]

    float *om, *wtd, *wto;
    cudaGetSymbolAddress((void**)&om,  g_om);
    cudaGetSymbolAddress((void**)&wtd, g_wt_dcn);
    cudaGetSymbolAddress((void**)&wto, g_wt_om);

    const int smem_conv = 64 * 128 * 4 + 2 * 64 * 64 * 4;   // 65536
    const int smem_dcn  = 64 * 256 * 4 + 2 * 64 * 64 * 4;   // 98304
    cudaFuncSetAttribute(k_fused<128, false, 3>,
                         cudaFuncAttributeMaxDynamicSharedMemorySize, smem_conv);
    cudaFuncSetAttribute(k_fused<256, true, 2>,
                         cudaFuncAttributeMaxDynamicSharedMemorySize, smem_dcn);

    // weight transposes (tiny)
    k_transpose_dcn<<<2304, 256>>>(w_dcn, wtd);
    k_transpose_om<<<1152, 256>>>(w_om, wto);

    // offset-mask conv: om = conv3x3(x, w_om) + b_om (raw; sigmoid on read)
    k_fused<128, false, 3><<<1250, 256, smem_conv>>>(x, wto, nullptr, b_om, om, OMCH);

    // modulated deformable conv + ReLU
    k_fused<256, true, 2><<<1250, 256, smem_dcn>>>(x, wtd, om, nullptr, out, 256);
}